// round 1
// baseline (speedup 1.0000x reference)
#include <cuda_runtime.h>
#include <cuda_bf16.h>

// wACSFRad: radial ACSF with segment-sum over edge receivers.
//   out[recv, k] += exp(-eta[t,k]*(rij-mu[t,k])^2) * fc(rij) * float(z[send])
//   t = z[recv], rij = |xyz[recv]-xyz[send]|, fc = 0.5*(cos(min(rij,8)*pi/8)+1)
//
// Inputs (metadata order):
//   d_in[0] z      int32  [100000]
//   d_in[1] xyz    f32    [100000,3]
//   d_in[2] eij    int32  [3200000,2]  (recv, send)
//   d_in[3] eta_mu f32    [118,22,2]   (eta, mu) pairs
// Output: f32 [100000,22]

#define N_TYPES 118
#define N_PARAMS 22
#define TBL_F4 (N_TYPES * (N_PARAMS / 2))   // 1298 float4 = 20768 bytes

// Vectorized global reductions (sm_90+): cuts L2 atomic op count 22 -> 6 per edge.
__device__ __forceinline__ void red_v4(float* p, float a, float b, float c, float d) {
    asm volatile("red.global.add.v4.f32 [%0], {%1, %2, %3, %4};"
                 :: "l"(p), "f"(a), "f"(b), "f"(c), "f"(d) : "memory");
}
__device__ __forceinline__ void red_v2(float* p, float a, float b) {
    asm volatile("red.global.add.v2.f32 [%0], {%1, %2};"
                 :: "l"(p), "f"(a), "f"(b) : "memory");
}

__global__ void __launch_bounds__(256, 3) wacsf_rad_kernel(
    const int*    __restrict__ z,
    const float*  __restrict__ xyz,
    const int2*   __restrict__ eij,
    const float4* __restrict__ eta_mu,   // (eta0, mu0, eta1, mu1) per float4
    float*        __restrict__ out,
    int n_edges)
{
    __shared__ float4 tbl[TBL_F4];
    for (int i = threadIdx.x; i < TBL_F4; i += blockDim.x)
        tbl[i] = eta_mu[i];
    __syncthreads();

    const float PI_OVER_CUT = 0.39269908169872414f;  // pi / 8

    const int stride = gridDim.x * blockDim.x;
    for (int e = blockIdx.x * blockDim.x + threadIdx.x; e < n_edges; e += stride) {
        const int2 rs = __ldg(&eij[e]);
        const int recv = rs.x;
        const int send = rs.y;

        // gather coordinates (L2-resident)
        const float xi0 = __ldg(xyz + 3 * recv + 0);
        const float xi1 = __ldg(xyz + 3 * recv + 1);
        const float xi2 = __ldg(xyz + 3 * recv + 2);
        const float xj0 = __ldg(xyz + 3 * send + 0);
        const float xj1 = __ldg(xyz + 3 * send + 1);
        const float xj2 = __ldg(xyz + 3 * send + 2);

        const float dx = xi0 - xj0;
        const float dy = xi1 - xj1;
        const float dz = xi2 - xj2;
        const float r2 = fmaf(dx, dx, fmaf(dy, dy, dz * dz));
        const float rij = sqrtf(r2);

        // cosine cutoff (rij >= 0 so clip is just min with CUTOFF)
        const float fc = 0.5f * (__cosf(fminf(rij, 8.0f) * PI_OVER_CUT) + 1.0f);
        const float w  = (float)__ldg(z + send);
        const float s  = fc * w;

        const int t = __ldg(z + recv);
        const float4* row = tbl + t * (N_PARAMS / 2);

        float v[N_PARAMS];
        #pragma unroll
        for (int q = 0; q < N_PARAMS / 2; q++) {
            const float4 p = row[q];
            const float d0 = rij - p.y;
            const float d1 = rij - p.w;
            v[2 * q + 0] = s * __expf(-p.x * d0 * d0);
            v[2 * q + 1] = s * __expf(-p.z * d1 * d1);
        }

        // Row base = recv * 88 bytes: 16B-aligned iff recv is even.
        // Emit 5x v4 + 1x v2 with the v2 placed so every v4 is 16B-aligned.
        float* o = out + (long long)recv * N_PARAMS;
        if (recv & 1) {
            red_v2(o, v[0], v[1]);                       // offset  8 mod 16 (8B aligned)
            #pragma unroll
            for (int m = 0; m < 5; m++)                  // offsets 16B-aligned
                red_v4(o + 2 + 4 * m, v[2 + 4 * m], v[3 + 4 * m],
                                      v[4 + 4 * m], v[5 + 4 * m]);
        } else {
            #pragma unroll
            for (int m = 0; m < 5; m++)                  // offsets 16B-aligned
                red_v4(o + 4 * m, v[4 * m + 0], v[4 * m + 1],
                                  v[4 * m + 2], v[4 * m + 3]);
            red_v2(o + 20, v[20], v[21]);                // 16B-aligned anyway
        }
    }
}

extern "C" void kernel_launch(void* const* d_in, const int* in_sizes, int n_in,
                              void* d_out, int out_size) {
    const int*    z      = (const int*)   d_in[0];
    const float*  xyz    = (const float*) d_in[1];
    const int2*   eij    = (const int2*)  d_in[2];
    const float4* eta_mu = (const float4*)d_in[3];
    float*        out    = (float*)d_out;

    const int n_edges = in_sizes[2] / 2;

    // d_out is poisoned; the reduction needs zeros. Memset node is capturable.
    cudaMemsetAsync(d_out, 0, (size_t)out_size * sizeof(float), 0);

    // Persistent grid: 148 SMs x 3 CTAs (smem-limited: 20.8KB table per CTA).
    const int threads = 256;
    int blocks = 444;
    const int needed = (n_edges + threads - 1) / threads;
    if (needed < blocks) blocks = needed;

    wacsf_rad_kernel<<<blocks, threads>>>(z, xyz, eij, eta_mu, out, n_edges);
}

// round 2
// speedup vs baseline: 1.1603x; 1.1603x over previous
#include <cuda_runtime.h>
#include <cuda_bf16.h>

// wACSFRad: radial ACSF with segment-sum over edge receivers.
// R2: pack (x,y,z,float(type)) per node into a float4 scratch array so each
// per-edge gather is ONE 16B-aligned LDG.128 (1 sector, 1 wavefront/lane)
// instead of 4 divergent scalar LDGs. Fused exp+red loop to cut registers,
// occupancy raised to 4 CTAs/SM.
//
// Inputs (metadata order):
//   d_in[0] z      int32  [100000]
//   d_in[1] xyz    f32    [100000,3]
//   d_in[2] eij    int32  [3200000,2]  (recv, send)
//   d_in[3] eta_mu f32    [118,22,2]   (eta, mu) pairs
// Output: f32 [100000,22]

#define N_NODES_MAX 100000
#define N_TYPES 118
#define N_PARAMS 22
#define TBL_F4 (N_TYPES * (N_PARAMS / 2))   // 1298 float4 = 20768 bytes

// Static scratch: packed node record (x, y, z, float(type)). 1.6 MB.
__device__ float4 g_xyzw[N_NODES_MAX];

__device__ __forceinline__ void red_v4(float* p, float a, float b, float c, float d) {
    asm volatile("red.global.add.v4.f32 [%0], {%1, %2, %3, %4};"
                 :: "l"(p), "f"(a), "f"(b), "f"(c), "f"(d) : "memory");
}
__device__ __forceinline__ void red_v2(float* p, float a, float b) {
    asm volatile("red.global.add.v2.f32 [%0], {%1, %2};"
                 :: "l"(p), "f"(a), "f"(b) : "memory");
}

__global__ void pack_nodes_kernel(const int* __restrict__ z,
                                  const float* __restrict__ xyz, int n) {
    int i = blockIdx.x * blockDim.x + threadIdx.x;
    if (i < n) {
        float4 v;
        v.x = xyz[3 * i + 0];
        v.y = xyz[3 * i + 1];
        v.z = xyz[3 * i + 2];
        v.w = (float)z[i];       // exact for 0..117; doubles as weight and type
        g_xyzw[i] = v;
    }
}

__global__ void __launch_bounds__(256, 4) wacsf_rad_kernel(
    const int2*   __restrict__ eij,
    const float4* __restrict__ eta_mu,   // (eta0, mu0, eta1, mu1) per float4
    float*        __restrict__ out,
    int n_edges)
{
    __shared__ float4 tbl[TBL_F4];
    for (int i = threadIdx.x; i < TBL_F4; i += blockDim.x)
        tbl[i] = eta_mu[i];
    __syncthreads();

    const float PI_OVER_CUT = 0.39269908169872414f;  // pi / 8

    const int stride = gridDim.x * blockDim.x;
    for (int e = blockIdx.x * blockDim.x + threadIdx.x; e < n_edges; e += stride) {
        const int2 rs = __ldg(&eij[e]);
        const int recv = rs.x;
        const int send = rs.y;

        // one 16B gather per node: 1 sector, 1 wavefront per lane
        const float4 a = __ldg(&g_xyzw[recv]);
        const float4 b = __ldg(&g_xyzw[send]);

        const float dx = a.x - b.x;
        const float dy = a.y - b.y;
        const float dz = a.z - b.z;
        const float rij = sqrtf(fmaf(dx, dx, fmaf(dy, dy, dz * dz)));

        const float fc = 0.5f * (__cosf(fminf(rij, 8.0f) * PI_OVER_CUT) + 1.0f);
        const float s  = fc * b.w;                 // b.w = float(z[send])
        const int   t  = (int)a.w;                 // a.w = float(z[recv])

        const float4* row = tbl + t * (N_PARAMS / 2);
        float* o = out + (long long)recv * N_PARAMS;

        // Row base = recv*88B: 16B-aligned iff recv even. Fused compute+red,
        // v2 placed so every v4 stays 16B-aligned.
        if (!(recv & 1)) {
            #pragma unroll
            for (int m = 0; m < 5; m++) {
                const float4 p0 = row[2 * m];
                const float4 p1 = row[2 * m + 1];
                const float d0 = rij - p0.y, d1 = rij - p0.w;
                const float d2 = rij - p1.y, d3 = rij - p1.w;
                red_v4(o + 4 * m,
                       s * __expf(-p0.x * d0 * d0), s * __expf(-p0.z * d1 * d1),
                       s * __expf(-p1.x * d2 * d2), s * __expf(-p1.z * d3 * d3));
            }
            const float4 p = row[10];
            const float d0 = rij - p.y, d1 = rij - p.w;
            red_v2(o + 20, s * __expf(-p.x * d0 * d0), s * __expf(-p.z * d1 * d1));
        } else {
            const float4 p = row[0];
            const float e0 = rij - p.y, e1 = rij - p.w;
            red_v2(o, s * __expf(-p.x * e0 * e0), s * __expf(-p.z * e1 * e1));
            #pragma unroll
            for (int m = 0; m < 5; m++) {
                const float4 p0 = row[2 * m + 1];
                const float4 p1 = row[2 * m + 2];
                const float d0 = rij - p0.y, d1 = rij - p0.w;
                const float d2 = rij - p1.y, d3 = rij - p1.w;
                red_v4(o + 2 + 4 * m,
                       s * __expf(-p0.x * d0 * d0), s * __expf(-p0.z * d1 * d1),
                       s * __expf(-p1.x * d2 * d2), s * __expf(-p1.z * d3 * d3));
            }
        }
    }
}

extern "C" void kernel_launch(void* const* d_in, const int* in_sizes, int n_in,
                              void* d_out, int out_size) {
    const int*    z      = (const int*)   d_in[0];
    const float*  xyz    = (const float*) d_in[1];
    const int2*   eij    = (const int2*)  d_in[2];
    const float4* eta_mu = (const float4*)d_in[3];
    float*        out    = (float*)d_out;

    const int n_nodes = in_sizes[0];
    const int n_edges = in_sizes[2] / 2;

    cudaMemsetAsync(d_out, 0, (size_t)out_size * sizeof(float), 0);

    pack_nodes_kernel<<<(n_nodes + 255) / 256, 256>>>(z, xyz, n_nodes);

    const int threads = 256;
    int blocks = 148 * 4;                     // persistent: 4 CTAs/SM
    const int needed = (n_edges + threads - 1) / threads;
    if (needed < blocks) blocks = needed;

    wacsf_rad_kernel<<<blocks, threads>>>(eij, eta_mu, out, n_edges);
}

// round 3
// speedup vs baseline: 1.6903x; 1.4568x over previous
#include <cuda_runtime.h>
#include <cuda_bf16.h>

// wACSFRad R3: bucket-CSR rebuild per call -> atomic-free output.
//  phase 1 pack:    xyzw[i] = (x,y,z,float(z_i)); cursor[i]=0
//  phase 2 scatter: bucket[recv*CAP + atomicAdd(cursor[recv],1)] = send
//  phase 3 compute: 4 lanes/node; lanes gather 4 edges, broadcast (rij,s) via
//                   shfl, each lane accumulates params k=r,r+4,... in regs,
//                   plain coalesced store. No output atomics.
//
// Inputs (metadata order):
//   d_in[0] z      int32  [100000]
//   d_in[1] xyz    f32    [100000,3]
//   d_in[2] eij    int32  [3200000,2]  (recv, send)
//   d_in[3] eta_mu f32    [118,22,2]
// Output: f32 [100000,22]

#define N_NODES_MAX 100000
#define N_PARAMS 22
#define CAP 128                 // bucket capacity; degrees ~Poisson(32), max≈66
#define PI_OVER_CUT 0.39269908169872414f

__device__ float4 g_xyzw[N_NODES_MAX];
__device__ int    g_cursor[N_NODES_MAX];
__device__ int    g_bucket[(long long)N_NODES_MAX * CAP];

__global__ void pack_nodes_kernel(const int* __restrict__ z,
                                  const float* __restrict__ xyz, int n) {
    int i = blockIdx.x * blockDim.x + threadIdx.x;
    if (i < n) {
        float4 v;
        v.x = xyz[3 * i + 0];
        v.y = xyz[3 * i + 1];
        v.z = xyz[3 * i + 2];
        v.w = (float)z[i];          // exact for 0..117; weight AND type
        g_xyzw[i] = v;
        g_cursor[i] = 0;
    }
}

__global__ void __launch_bounds__(256) scatter_kernel(
    const int2* __restrict__ eij,
    const float2* __restrict__ eta_mu2,   // (eta,mu) pairs
    float* __restrict__ out,
    int n_edges)
{
    int e = blockIdx.x * blockDim.x + threadIdx.x;
    if (e >= n_edges) return;
    const int2 rs = __ldg(&eij[e]);
    const int pos = atomicAdd(&g_cursor[rs.x], 1);
    if (pos < CAP) {
        g_bucket[(long long)rs.x * CAP + pos] = rs.y;
    } else {
        // Overflow fallback (never taken for Poisson(32) degrees): direct atomics.
        const float4 a = __ldg(&g_xyzw[rs.x]);
        const float4 b = __ldg(&g_xyzw[rs.y]);
        const float dx = a.x - b.x, dy = a.y - b.y, dz = a.z - b.z;
        const float rij = sqrtf(fmaf(dx, dx, fmaf(dy, dy, dz * dz)));
        const float s = 0.5f * (__cosf(fminf(rij, 8.0f) * PI_OVER_CUT) + 1.0f) * b.w;
        const int t = (int)a.w;
        float* o = out + (long long)rs.x * N_PARAMS;
        for (int k = 0; k < N_PARAMS; k++) {
            const float2 p = __ldg(&eta_mu2[t * N_PARAMS + k]);
            const float d = rij - p.y;
            atomicAdd(o + k, s * __expf(-p.x * d * d));
        }
    }
}

__global__ void __launch_bounds__(256) compute_kernel(
    const float2* __restrict__ eta_mu2,
    float* __restrict__ out,
    int n_nodes)
{
    const int gid = blockIdx.x * blockDim.x + threadIdx.x;
    int node = gid >> 2;
    const int r = gid & 3;                         // lane within 4-lane group
    if (node >= n_nodes) node = n_nodes - 1;       // clamp: benign duplicate work
    const unsigned lane = threadIdx.x & 31u;
    const unsigned lane_base = lane & ~3u;

    const float4 a = __ldg(&g_xyzw[node]);
    const int t = (int)a.w;
    const int deg_raw = g_cursor[node];
    const int deg = deg_raw < CAP ? deg_raw : CAP;
    const long long base = (long long)node * CAP;

    // lane r owns params k = r, r+4, ..., held in registers for the whole node
    float eta[6], mu[6];
    #pragma unroll
    for (int j = 0; j < 6; j++) {
        const int k = r + 4 * j;
        if (k < N_PARAMS) {
            const float2 p = __ldg(&eta_mu2[t * N_PARAMS + k]);
            eta[j] = p.x; mu[j] = p.y;
        } else { eta[j] = 0.0f; mu[j] = 0.0f; }    // exp(0)=1, never stored
    }
    float acc[6] = {0.f, 0.f, 0.f, 0.f, 0.f, 0.f};

    for (int e0 = 0; e0 < deg; e0 += 4) {
        const int e = e0 + r;
        float rij_l = 0.0f, s_l = 0.0f;
        if (e < deg) {
            const int send = __ldg(&g_bucket[base + e]);
            const float4 b = __ldg(&g_xyzw[send]);
            const float dx = a.x - b.x, dy = a.y - b.y, dz = a.z - b.z;
            rij_l = sqrtf(fmaf(dx, dx, fmaf(dy, dy, dz * dz)));
            s_l = 0.5f * (__cosf(fminf(rij_l, 8.0f) * PI_OVER_CUT) + 1.0f) * b.w;
        }
        #pragma unroll
        for (int j = 0; j < 4; j++) {
            const float rj = __shfl_sync(0xffffffffu, rij_l, lane_base + j);
            const float sj = __shfl_sync(0xffffffffu, s_l,  lane_base + j);
            #pragma unroll
            for (int q = 0; q < 6; q++) {
                const float d = rj - mu[q];
                acc[q] = fmaf(sj, __expf(-eta[q] * d * d), acc[q]);
            }
        }
    }

    float* o = out + (long long)node * N_PARAMS;
    if (deg_raw <= CAP) {
        #pragma unroll
        for (int j = 0; j < 6; j++) {
            const int k = r + 4 * j;
            if (k < N_PARAMS) o[k] = acc[j];       // plain coalesced store
        }
    } else {
        // node had overflow edges added via atomics in scatter; merge by add
        #pragma unroll
        for (int j = 0; j < 6; j++) {
            const int k = r + 4 * j;
            if (k < N_PARAMS) atomicAdd(o + k, acc[j]);
        }
    }
}

extern "C" void kernel_launch(void* const* d_in, const int* in_sizes, int n_in,
                              void* d_out, int out_size) {
    const int*    z       = (const int*)   d_in[0];
    const float*  xyz     = (const float*) d_in[1];
    const int2*   eij     = (const int2*)  d_in[2];
    const float2* eta_mu2 = (const float2*)d_in[3];
    float*        out     = (float*)d_out;

    const int n_nodes = in_sizes[0];
    const int n_edges = in_sizes[2] / 2;

    // zero for (never-taken) overflow-atomic path; plain stores overwrite anyway
    cudaMemsetAsync(d_out, 0, (size_t)out_size * sizeof(float), 0);

    pack_nodes_kernel<<<(n_nodes + 255) / 256, 256>>>(z, xyz, n_nodes);
    scatter_kernel<<<(n_edges + 255) / 256, 256>>>(eij, eta_mu2, out, n_edges);

    const int threads_needed = n_nodes * 4;
    compute_kernel<<<(threads_needed + 255) / 256, 256>>>(eta_mu2, out, n_nodes);
}

// round 4
// speedup vs baseline: 1.7697x; 1.0470x over previous
#include <cuda_runtime.h>
#include <cuda_bf16.h>

// wACSFRad R4: bucket-CSR, atomic-free output.
//  pack:    xyzw[i]=(x,y,z,float(z_i)); cursor[i]=0
//  scatter: 2 edges/thread (int4); bucket[recv*CAP + atomicAdd(cursor)] = send
//  compute: 4 lanes/node, 8 edges per group-iter (2 chains/lane for ILP),
//           shfl-broadcast (rij,s), per-lane register accumulators, plain store.
//
// Inputs: z i32[100000], xyz f32[100000,3], eij i32[3200000,2], eta_mu f32[118,22,2]
// Output: f32 [100000,22]

#define N_NODES_MAX 100000
#define N_PARAMS 22
#define CAP 128
#define PI_OVER_CUT 0.39269908169872414f

__device__ float4 g_xyzw[N_NODES_MAX + 1];
__device__ int    g_cursor[N_NODES_MAX];
__device__ int    g_bucket[(long long)N_NODES_MAX * CAP];

__global__ void pack_nodes_kernel(const int* __restrict__ z,
                                  const float* __restrict__ xyz, int n) {
    int i = blockIdx.x * blockDim.x + threadIdx.x;
    if (i < n) {
        float4 v;
        v.x = xyz[3 * i + 0];
        v.y = xyz[3 * i + 1];
        v.z = xyz[3 * i + 2];
        v.w = (float)z[i];          // exact for 0..117; weight AND type
        g_xyzw[i] = v;
        g_cursor[i] = 0;
    }
}

__device__ __forceinline__ void scatter_one(int recv, int send,
                                            const float2* __restrict__ eta_mu2,
                                            float* __restrict__ out) {
    const int pos = atomicAdd(&g_cursor[recv], 1);
    if (pos < CAP) {
        g_bucket[(long long)recv * CAP + pos] = send;
    } else {
        // overflow fallback (never taken for Poisson(32) degrees)
        const float4 a = __ldg(&g_xyzw[recv]);
        const float4 b = __ldg(&g_xyzw[send]);
        const float dx = a.x - b.x, dy = a.y - b.y, dz = a.z - b.z;
        const float rij = sqrtf(fmaf(dx, dx, fmaf(dy, dy, dz * dz)));
        const float s = 0.5f * (__cosf(fminf(rij, 8.0f) * PI_OVER_CUT) + 1.0f) * b.w;
        const int t = (int)a.w;
        float* o = out + (long long)recv * N_PARAMS;
        for (int k = 0; k < N_PARAMS; k++) {
            const float2 p = __ldg(&eta_mu2[t * N_PARAMS + k]);
            const float d = rij - p.y;
            atomicAdd(o + k, s * __expf(-p.x * d * d));
        }
    }
}

__global__ void __launch_bounds__(256) scatter_kernel(
    const int4* __restrict__ eij2,        // 2 edges per int4
    const int2* __restrict__ eij,         // scalar view for odd tail
    const float2* __restrict__ eta_mu2,
    float* __restrict__ out,
    int n_pairs, int n_edges)
{
    const int i = blockIdx.x * blockDim.x + threadIdx.x;
    if (i < n_pairs) {
        const int4 v = __ldg(&eij2[i]);
        scatter_one(v.x, v.y, eta_mu2, out);
        scatter_one(v.z, v.w, eta_mu2, out);
    }
    if (i == 0 && (n_edges & 1)) {
        const int2 t = __ldg(&eij[n_edges - 1]);
        scatter_one(t.x, t.y, eta_mu2, out);
    }
}

__global__ void __launch_bounds__(256) compute_kernel(
    const float2* __restrict__ eta_mu2,
    float* __restrict__ out,
    int n_nodes)
{
    const int gid = blockIdx.x * blockDim.x + threadIdx.x;
    int node = gid >> 2;
    const int r = gid & 3;
    if (node >= n_nodes) node = n_nodes - 1;       // benign duplicate work
    const unsigned lane_base = (threadIdx.x & 31u) & ~3u;

    const float4 a = __ldg(&g_xyzw[node]);
    const int t = (int)a.w;
    const int deg_raw = g_cursor[node];
    const int deg = deg_raw < CAP ? deg_raw : CAP;
    const long long base = (long long)node * CAP;

    float eta[6], mu[6];
    #pragma unroll
    for (int j = 0; j < 6; j++) {
        const int k = r + 4 * j;
        if (k < N_PARAMS) {
            const float2 p = __ldg(&eta_mu2[t * N_PARAMS + k]);
            eta[j] = p.x; mu[j] = p.y;
        } else { eta[j] = 0.0f; mu[j] = 0.0f; }
    }
    float acc[6] = {0.f, 0.f, 0.f, 0.f, 0.f, 0.f};

    // 8 edges per group-iteration: two independent load chains per lane.
    for (int e0 = 0; e0 < deg; e0 += 8) {
        const int eA = e0 + r;
        const int eB = e0 + 4 + r;

        float rijA = 0.f, sA = 0.f, rijB = 0.f, sB = 0.f;
        // issue both bucket loads first (independent), then both gathers
        int sendA = -1, sendB = -1;
        if (eA < deg) sendA = __ldg(&g_bucket[base + eA]);
        if (eB < deg) sendB = __ldg(&g_bucket[base + eB]);
        float4 bA, bB;
        if (sendA >= 0) bA = __ldg(&g_xyzw[sendA]);
        if (sendB >= 0) bB = __ldg(&g_xyzw[sendB]);
        if (sendA >= 0) {
            const float dx = a.x - bA.x, dy = a.y - bA.y, dz = a.z - bA.z;
            rijA = sqrtf(fmaf(dx, dx, fmaf(dy, dy, dz * dz)));
            sA = 0.5f * (__cosf(fminf(rijA, 8.0f) * PI_OVER_CUT) + 1.0f) * bA.w;
        }
        if (sendB >= 0) {
            const float dx = a.x - bB.x, dy = a.y - bB.y, dz = a.z - bB.z;
            rijB = sqrtf(fmaf(dx, dx, fmaf(dy, dy, dz * dz)));
            sB = 0.5f * (__cosf(fminf(rijB, 8.0f) * PI_OVER_CUT) + 1.0f) * bB.w;
        }

        #pragma unroll
        for (int j = 0; j < 4; j++) {
            const float rj = __shfl_sync(0xffffffffu, rijA, lane_base + j);
            const float sj = __shfl_sync(0xffffffffu, sA,  lane_base + j);
            #pragma unroll
            for (int q = 0; q < 6; q++) {
                const float d = rj - mu[q];
                acc[q] = fmaf(sj, __expf(-eta[q] * d * d), acc[q]);
            }
        }
        #pragma unroll
        for (int j = 0; j < 4; j++) {
            const float rj = __shfl_sync(0xffffffffu, rijB, lane_base + j);
            const float sj = __shfl_sync(0xffffffffu, sB,  lane_base + j);
            #pragma unroll
            for (int q = 0; q < 6; q++) {
                const float d = rj - mu[q];
                acc[q] = fmaf(sj, __expf(-eta[q] * d * d), acc[q]);
            }
        }
    }

    float* o = out + (long long)node * N_PARAMS;
    if (deg_raw <= CAP) {
        #pragma unroll
        for (int j = 0; j < 6; j++) {
            const int k = r + 4 * j;
            if (k < N_PARAMS) o[k] = acc[j];
        }
    } else {
        #pragma unroll
        for (int j = 0; j < 6; j++) {
            const int k = r + 4 * j;
            if (k < N_PARAMS) atomicAdd(o + k, acc[j]);
        }
    }
}

extern "C" void kernel_launch(void* const* d_in, const int* in_sizes, int n_in,
                              void* d_out, int out_size) {
    const int*    z       = (const int*)   d_in[0];
    const float*  xyz     = (const float*) d_in[1];
    const int2*   eij     = (const int2*)  d_in[2];
    const int4*   eij2    = (const int4*)  d_in[2];
    const float2* eta_mu2 = (const float2*)d_in[3];
    float*        out     = (float*)d_out;

    const int n_nodes = in_sizes[0];
    const int n_edges = in_sizes[2] / 2;
    const int n_pairs = n_edges / 2;

    cudaMemsetAsync(d_out, 0, (size_t)out_size * sizeof(float), 0);

    pack_nodes_kernel<<<(n_nodes + 255) / 256, 256>>>(z, xyz, n_nodes);
    scatter_kernel<<<(n_pairs + 255) / 256, 256>>>(eij2, eij, eta_mu2, out,
                                                   n_pairs, n_edges);

    const int threads_needed = n_nodes * 4;
    compute_kernel<<<(threads_needed + 255) / 256, 256>>>(eta_mu2, out, n_nodes);
}